// round 6
// baseline (speedup 1.0000x reference)
#include <cuda_runtime.h>
#include <cuda_bf16.h>
#include <math.h>
#include <stdint.h>

#ifndef M_PI
#define M_PI 3.14159265358979323846
#endif

#define NLAT 256
#define NLON 256
#define LMAX 128
#define MMAX 129
#define CIN 32
#define COUT 32
#define BATCH 8
#define NPLANE 258            // 2*MMAX
#define KPAD 264              // padded plane count for S7 (mult of 8)
#define BC (BATCH*CIN)        // 256
#define NCOEF (2*LMAX*MMAX)   // 33024
#define ROWS_BCK (BC*NLAT)    // 65536

typedef __nv_bfloat16 bf16;

// ---------------- device scratch ----------------
__device__ float g_w[NLAT];
__device__ float g_seed[MMAX];
__device__ float g_ab[MMAX*LMAX*2];

__device__ __align__(256) bf16 g_x16h[(size_t)ROWS_BCK*NLON];
__device__ __align__(256) bf16 g_x16l[(size_t)ROWS_BCK*NLON];
__device__ __align__(256) bf16 g_F16h[NPLANE*NLON];
__device__ __align__(256) bf16 g_F16l[NPLANE*NLON];
__device__ __align__(256) bf16 g_G16h[NLON*KPAD];
__device__ __align__(256) bf16 g_G16l[NLON*KPAD];
__device__ __align__(256) bf16 g_PWh[MMAX*LMAX*NLAT];   // [m][l][k]
__device__ __align__(256) bf16 g_PWl[MMAX*LMAX*NLAT];
__device__ __align__(256) bf16 g_PTh[MMAX*NLAT*LMAX];   // [m][k][l]
__device__ __align__(256) bf16 g_PTl[MMAX*NLAT*LMAX];

__device__ __align__(256) float g_XH[(size_t)NPLANE*ROWS_BCK];   // [plane][bc*256+k]
__device__ __align__(256) bf16  g_XHh[(size_t)NPLANE*ROWS_BCK];
__device__ __align__(256) bf16  g_XHl[(size_t)NPLANE*ROWS_BCK];
__device__ __align__(256) float g_SPT[(size_t)NPLANE*BC*LMAX];   // [plane][bc][l]
__device__ __align__(256) float g_SP [(size_t)BC*LMAX*NPLANE];   // [bc][x]
__device__ __align__(256) float g_OUT[(size_t)BC*NCOEF];         // [bo][x]
__device__ __align__(256) float g_OUTT[(size_t)NPLANE*BC*LMAX];  // [plane][bo][l]
__device__ __align__(256) bf16  g_OTh[(size_t)NPLANE*BC*LMAX];
__device__ __align__(256) bf16  g_OTl[(size_t)NPLANE*BC*LMAX];
__device__ __align__(256) float g_RR[(size_t)NPLANE*ROWS_BCK];   // [plane][bo*256+k]
__device__ __align__(256) bf16  g_RTh[(size_t)ROWS_BCK*KPAD];    // [bckl][plane] ld 264
__device__ __align__(256) bf16  g_RTl[(size_t)ROWS_BCK*KPAD];

// ---------------- helpers ----------------
__device__ __forceinline__ void splitw(float v, bf16& h, bf16& l) {
    h = __float2bfloat16(v);
    l = __float2bfloat16(v - __bfloat162float(h));
}
__device__ __forceinline__ uint32_t SWZ(uint32_t off) { return off ^ ((off >> 3) & 0x70); }
__device__ __forceinline__ uint32_t smem_u32(const void* p) {
    uint32_t a;
    asm("{ .reg .u64 t; cvta.to.shared.u64 t, %1; cvt.u32.u64 %0, t; }" : "=r"(a) : "l"(p));
    return a;
}
__device__ __forceinline__ void ldsm4(uint32_t* r, uint32_t addr) {
    asm volatile("ldmatrix.sync.aligned.m8n8.x4.shared.b16 {%0,%1,%2,%3}, [%4];"
        : "=r"(r[0]), "=r"(r[1]), "=r"(r[2]), "=r"(r[3]) : "r"(addr));
}
__device__ __forceinline__ void mma_bf16(float* c, const uint32_t* a, uint32_t b0, uint32_t b1) {
    asm volatile("mma.sync.aligned.m16n8k16.row.col.f32.bf16.bf16.f32 "
        "{%0,%1,%2,%3}, {%4,%5,%6,%7}, {%8,%9}, {%0,%1,%2,%3};"
        : "+f"(c[0]), "+f"(c[1]), "+f"(c[2]), "+f"(c[3])
        : "r"(a[0]), "r"(a[1]), "r"(a[2]), "r"(a[3]), "r"(b0), "r"(b1));
}

// ---------------- table builders ----------------
__global__ void tab_weights() {
    int j = threadIdx.x;
    double tj = M_PI * (double)j / (double)(NLAT - 1);
    double S = 0.0;
    for (int k = 1; k <= (NLAT - 1) / 2; k++)
        S += cos(2.0 * tj * (double)k) * (2.0 / (4.0 * (double)k * k - 1.0));
    double c = (j == 0 || j == NLAT - 1) ? 1.0 : 2.0;
    g_w[j] = (float)(c / (double)(NLAT - 1) * (1.0 - S));
}

__global__ void tab_ab() {
    int t = blockIdx.x * blockDim.x + threadIdx.x;
    if (t >= MMAX * LMAX) return;
    int m = t / LMAX, l = t % LMAX;
    if (l == 0)
        g_seed[m] = (m >= 1) ? (float)sqrt((2.0 * m + 1.0) / (2.0 * m)) : 0.f;
    float a = 0.f, b = 0.f;
    if (l >= m + 2) {
        double ld = l, md = m;
        a = (float)sqrt((4.0 * ld * ld - 1.0) / (ld * ld - md * md));
        b = (float)sqrt(((ld - 1.0) * (ld - 1.0) - md * md) /
                        (4.0 * (ld - 1.0) * (ld - 1.0) - 1.0));
    }
    g_ab[t * 2] = a;
    g_ab[t * 2 + 1] = b;
}

// writes PCTW (weighted, [m][l][k]) and PCT_T ([m][k][l]) as bf16 hi/lo pairs
__global__ void tab_leg() {
    int t = blockIdx.x * blockDim.x + threadIdx.x;
    if (t >= MMAX * NLAT) return;
    int m = t / NLAT, k = t % NLAT;
    double td = M_PI * (double)k / (double)(NLAT - 1);
    float ct = (float)cos(td), st = (float)sin(td);
    float w = g_w[k];
    float pmm = 0.28209479177387814f;  // 1/sqrt(4*pi)
    for (int mm = 1; mm <= m; mm++) pmm *= -g_seed[mm] * st;

    size_t wi = (size_t)(m * LMAX) * NLAT + k;   // stride NLAT per l
    size_t ti = ((size_t)m * NLAT + k) * LMAX;   // stride 1 per l
    bf16 h, l2;
    for (int l = 0; l < m && l < LMAX; l++) {
        g_PWh[wi] = __float2bfloat16(0.f); g_PWl[wi] = __float2bfloat16(0.f);
        g_PTh[ti + l] = __float2bfloat16(0.f); g_PTl[ti + l] = __float2bfloat16(0.f);
        wi += NLAT;
    }
    if (m < LMAX) {
        float pm2 = pmm;
        splitw(pm2 * w, h, l2); g_PWh[wi] = h; g_PWl[wi] = l2;
        splitw(pm2, h, l2);     g_PTh[ti + m] = h; g_PTl[ti + m] = l2;
        wi += NLAT;
        if (m + 1 < LMAX) {
            float pm1 = sqrtf(2.f * m + 3.f) * ct * pm2;
            splitw(pm1 * w, h, l2); g_PWh[wi] = h; g_PWl[wi] = l2;
            splitw(pm1, h, l2);     g_PTh[ti + m + 1] = h; g_PTl[ti + m + 1] = l2;
            wi += NLAT;
            for (int l = m + 2; l < LMAX; l++) {
                float a = g_ab[(m * LMAX + l) * 2];
                float b = g_ab[(m * LMAX + l) * 2 + 1];
                float pn = a * (ct * pm1 - b * pm2);
                splitw(pn * w, h, l2); g_PWh[wi] = h; g_PWl[wi] = l2;
                splitw(pn, h, l2);     g_PTh[ti + l] = h; g_PTl[ti + l] = l2;
                wi += NLAT;
                pm2 = pm1; pm1 = pn;
            }
        }
    }
}

// Forward DFT matrix, plane-major: Ft[2m+r][n], bf16 pair
__global__ void tab_F() {
    int t = blockIdx.x * blockDim.x + threadIdx.x;
    if (t >= NPLANE * NLON) return;
    int p = t / NLON, n = t % NLON;
    int m = p >> 1, r = p & 1;
    double ang = 2.0 * M_PI * (double)((m * n) & (NLON - 1)) / (double)NLON;
    double s = 2.0 * M_PI / (double)NLON;
    float v = (float)(r == 0 ? s * cos(ang) : -s * sin(ang));
    bf16 h, l; splitw(v, h, l);
    g_F16h[t] = h; g_F16l[t] = l;
}

// Inverse DFT matrix, lon-major: Gt[n][2m+r], ld=KPAD, zero-padded
__global__ void tab_G() {
    int t = blockIdx.x * blockDim.x + threadIdx.x;
    if (t >= NLON * KPAD) return;
    int n = t / KPAD, p = t % KPAD;
    float v = 0.f;
    if (p < NPLANE) {
        int m = p >> 1, r = p & 1;
        double c = (m == 0 || m == MMAX - 1) ? 1.0 : 2.0;
        double ang = 2.0 * M_PI * (double)((m * n) & (NLON - 1)) / (double)NLON;
        v = (float)(r == 0 ? c * cos(ang) : -c * sin(ang));
    }
    bf16 h, l; splitw(v, h, l);
    g_G16h[t] = h; g_G16l[t] = l;
}

// ---------------- fp32 -> bf16 hi/lo convert (vectorized) ----------------
__global__ void cvt32(const float* __restrict__ in, bf16* __restrict__ hi,
                      bf16* __restrict__ lo, int n4) {
    int i = blockIdx.x * blockDim.x + threadIdx.x;
    if (i >= n4) return;
    float4 v = reinterpret_cast<const float4*>(in)[i];
    __nv_bfloat162 h0 = __floats2bfloat162_rn(v.x, v.y);
    __nv_bfloat162 h1 = __floats2bfloat162_rn(v.z, v.w);
    __nv_bfloat162 l0 = __floats2bfloat162_rn(v.x - __bfloat162float(h0.x),
                                              v.y - __bfloat162float(h0.y));
    __nv_bfloat162 l1 = __floats2bfloat162_rn(v.z - __bfloat162float(h1.x),
                                              v.w - __bfloat162float(h1.y));
    reinterpret_cast<uint2*>(hi)[i] = make_uint2(*reinterpret_cast<uint32_t*>(&h0),
                                                 *reinterpret_cast<uint32_t*>(&h1));
    reinterpret_cast<uint2*>(lo)[i] = make_uint2(*reinterpret_cast<uint32_t*>(&l0),
                                                 *reinterpret_cast<uint32_t*>(&l1));
}

// ---------------- transpose + convert: RR[258][65536] -> RRT[65536][264] bf16 pair ----
__global__ void transcvt(const float* __restrict__ in, bf16* __restrict__ hi,
                         bf16* __restrict__ lo) {
    __shared__ float t[32][33];
    int c0 = blockIdx.x * 32;   // over ROWS_BCK
    int r0 = blockIdx.y * 32;   // over KPAD
    int tx = threadIdx.x;
    for (int j = threadIdx.y; j < 32; j += 8) {
        int r = r0 + j;
        t[j][tx] = (r < NPLANE) ? in[(size_t)r * ROWS_BCK + c0 + tx] : 0.f;
    }
    __syncthreads();
    for (int j = threadIdx.y; j < 32; j += 8) {
        int outc = r0 + tx;
        if (outc < KPAD) {
            float v = t[tx][j];
            bf16 h, l; splitw(v, h, l);
            size_t o = (size_t)(c0 + j) * KPAD + outc;
            hi[o] = h; lo[o] = l;
        }
    }
}

// ---------------- tensor-core GEMM v3: pre-split bf16 operands ----------------
// C[M,N] = (Ahi+Alo)*(Bhi+Blo) ~= Ahi*Bhi + Ahi*Blo + Alo*Bhi  (fp32 accum)
// A[m][k] rows M, ld lda; B[n][k] rows N, ld ldb. Block tile 128x128, BK=64.
// 256 threads, 8 warps (2 m x 4 n), warp tile 64x32.
// smem: a_hi @0, a_lo @16K, b_hi @32K, b_lo @48K (128 rows x 128B, SW128)
#define MM_SMEM 65536
#define OFF_ALO 16384u
#define OFF_BHI 32768u
#define OFF_BLO 49152u

template<bool CTRANS, bool BHALF>
__global__ void __launch_bounds__(256, 2) mmagemm3(
    const bf16* __restrict__ Ahi, const bf16* __restrict__ Alo,
    const bf16* __restrict__ Bhi, const bf16* __restrict__ Blo,
    float* __restrict__ C,
    int M, int N, int K, int lda, int ldb, int ldc, int sA, int sB, int sC)
{
    extern __shared__ char smem[];
    const uint32_t sbase = smem_u32(smem);
    const int tid = threadIdx.x;
    const int wid = tid >> 5;
    const int lane = tid & 31;

    int z = blockIdx.z;
    Ahi += (size_t)z * sA; Alo += (size_t)z * sA;
    size_t boff = (size_t)(BHALF ? (z >> 1) : z) * sB;
    Bhi += boff; Blo += boff;
    C += (size_t)z * sC;
    const int bm = blockIdx.x * 128;
    const int bn = blockIdx.y * 128;

    const int wm = wid & 1;   // m tile of 64
    const int wn = wid >> 1;  // n tile of 32

    float acc[4][4][4] = {};

    const uint32_t aBase = (uint32_t)((wm * 64 + (lane & 15)) * 128 + ((lane >> 4) << 4));
    const uint32_t bBase = (uint32_t)((wn * 32 + (lane & 15)) * 128 + ((lane >> 4) << 4));

    const int r  = tid >> 1;
    const int kh = (tid & 1) << 5;

    const int NK = (K + 63) >> 6;
    for (int kt = 0; kt < NK; kt++) {
        const int k0 = kt << 6;

        // ---- A tiles (hi+lo), row bm+r, cols k0+kh..+31 ----
        {
            size_t ro = (size_t)(bm + r) * lda + k0 + kh;
            const uint4* ph = reinterpret_cast<const uint4*>(Ahi + ro);
            const uint4* pl = reinterpret_cast<const uint4*>(Alo + ro);
            #pragma unroll
            for (int j = 0; j < 4; j++) {
                int gk = k0 + kh + j * 8;
                uint4 vh = make_uint4(0, 0, 0, 0), vl = make_uint4(0, 0, 0, 0);
                if (gk < K) { vh = ph[j]; vl = pl[j]; }
                uint32_t off = SWZ((uint32_t)(r * 128 + kh * 2 + j * 16));
                *reinterpret_cast<uint4*>(smem + off)           = vh;
                *reinterpret_cast<uint4*>(smem + OFF_ALO + off) = vl;
            }
        }
        // ---- B tiles (hi+lo), row bn+r ----
        {
            int gn = bn + r;
            bool nok = gn < N;
            size_t ro = (size_t)gn * ldb + k0 + kh;
            const uint4* ph = reinterpret_cast<const uint4*>(Bhi + ro);
            const uint4* pl = reinterpret_cast<const uint4*>(Blo + ro);
            #pragma unroll
            for (int j = 0; j < 4; j++) {
                int gk = k0 + kh + j * 8;
                uint4 vh = make_uint4(0, 0, 0, 0), vl = make_uint4(0, 0, 0, 0);
                if (nok && gk < K) { vh = ph[j]; vl = pl[j]; }
                uint32_t off = SWZ((uint32_t)(r * 128 + kh * 2 + j * 16));
                *reinterpret_cast<uint4*>(smem + OFF_BHI + off) = vh;
                *reinterpret_cast<uint4*>(smem + OFF_BLO + off) = vl;
            }
        }
        __syncthreads();

        // ---- MMA over 4 k-steps of 16 ----
        #pragma unroll
        for (int ks = 0; ks < 4; ks++) {
            uint32_t kb = (uint32_t)(ks * 32);

            uint32_t ah[4][4];
            #pragma unroll
            for (int mi = 0; mi < 4; mi++)
                ldsm4(ah[mi], sbase + SWZ(aBase + mi * 2048 + kb));

            uint32_t bh[4][2];
            #pragma unroll
            for (int g = 0; g < 2; g++) {
                uint32_t t[4];
                ldsm4(t, sbase + OFF_BHI + SWZ(bBase + g * 2048 + kb));
                bh[2 * g][0] = t[0]; bh[2 * g][1] = t[2];
                bh[2 * g + 1][0] = t[1]; bh[2 * g + 1][1] = t[3];
            }
            #pragma unroll
            for (int mi = 0; mi < 4; mi++)
                #pragma unroll
                for (int nb = 0; nb < 4; nb++)
                    mma_bf16(acc[mi][nb], ah[mi], bh[nb][0], bh[nb][1]);

            // Ahi * Blo
            #pragma unroll
            for (int g = 0; g < 2; g++) {
                uint32_t t[4];
                ldsm4(t, sbase + OFF_BLO + SWZ(bBase + g * 2048 + kb));
                #pragma unroll
                for (int mi = 0; mi < 4; mi++) {
                    mma_bf16(acc[mi][2 * g],     ah[mi], t[0], t[2]);
                    mma_bf16(acc[mi][2 * g + 1], ah[mi], t[1], t[3]);
                }
            }
            // Alo * Bhi
            #pragma unroll
            for (int mi = 0; mi < 4; mi++) {
                uint32_t al[4];
                ldsm4(al, sbase + OFF_ALO + SWZ(aBase + mi * 2048 + kb));
                #pragma unroll
                for (int nb = 0; nb < 4; nb++)
                    mma_bf16(acc[mi][nb], al, bh[nb][0], bh[nb][1]);
            }
        }
        __syncthreads();
    }

    // ---- epilogue ----
    #pragma unroll
    for (int mi = 0; mi < 4; mi++) {
        #pragma unroll
        for (int nb = 0; nb < 4; nb++) {
            int m0 = bm + wm * 64 + mi * 16 + (lane >> 2);
            int n0 = bn + wn * 32 + nb * 8 + ((lane & 3) << 1);
            float* a = acc[mi][nb];
            if (!CTRANS) {
                *reinterpret_cast<float2*>(&C[(size_t)m0 * ldc + n0]) =
                    make_float2(a[0], a[1]);
                *reinterpret_cast<float2*>(&C[(size_t)(m0 + 8) * ldc + n0]) =
                    make_float2(a[2], a[3]);
            } else {
                if (n0 < N) {
                    C[(size_t)n0 * ldc + m0]     = a[0];
                    C[(size_t)n0 * ldc + m0 + 8] = a[2];
                }
                if (n0 + 1 < N) {
                    C[(size_t)(n0 + 1) * ldc + m0]     = a[1];
                    C[(size_t)(n0 + 1) * ldc + m0 + 8] = a[3];
                }
            }
        }
    }
}

// ---------------- tiled transpose: in[R][Cc] -> out[Cc][R] ----------------
__global__ void transpose_k(const float* __restrict__ in, float* __restrict__ out,
                            int R, int Cc) {
    __shared__ float t[32][33];
    int c0 = blockIdx.x * 32, r0 = blockIdx.y * 32;
    int tx = threadIdx.x;
    for (int j = threadIdx.y; j < 32; j += 8) {
        int r = r0 + j, c = c0 + tx;
        if (r < R && c < Cc) t[j][tx] = in[(size_t)r * Cc + c];
    }
    __syncthreads();
    for (int j = threadIdx.y; j < 32; j += 8) {
        int c = c0 + j, r = r0 + tx;
        if (c < Cc && r < R) out[(size_t)c * R + r] = t[tx][j];
    }
}

// ---------------- channel mix ----------------
__global__ void __launch_bounds__(128) mix_k(const float* __restrict__ spec,
                                             const float* __restrict__ wgt,
                                             float* __restrict__ out) {
    __shared__ float s_sp[8][32][32];
    __shared__ float s_w[32][4][32];
    int x0 = blockIdx.x * 32;
    int tx = threadIdx.x, ty = threadIdx.y;
    int tid = ty * 32 + tx;
    int warp = tid >> 5, wl = tid & 31;
    for (int row = warp; row < 256; row += 4)
        s_sp[row >> 5][row & 31][wl] = spec[row * NCOEF + x0 + wl];
    for (int oc = 0; oc < 8; oc++) {
        __syncthreads();
        for (int r = warp; r < 128; r += 4) {
            int i = r >> 2, ol = r & 3;
            s_w[i][ol][wl] = wgt[(i * COUT + oc * 4 + ol) * NCOEF + x0 + wl];
        }
        __syncthreads();
        float acc[8] = {};
        #pragma unroll
        for (int i = 0; i < 32; i++) {
            float wv = s_w[i][ty][tx];
            #pragma unroll
            for (int b = 0; b < 8; b++) acc[b] += s_sp[b][i][tx] * wv;
        }
        int o = oc * 4 + ty;
        #pragma unroll
        for (int b = 0; b < 8; b++)
            out[(b * COUT + o) * NCOEF + x0 + tx] = acc[b];
    }
}

// ---------------- launch ----------------
extern "C" void kernel_launch(void* const* d_in, const int* in_sizes, int n_in,
                              void* d_out, int out_size) {
    const float* x   = (const float*)d_in[0];   // [8,32,256,256]
    const float* wgt = (const float*)d_in[1];   // [32,32,33024]
    float* y = (float*)d_out;                   // [8,32,256,256]

    bf16 *pXh, *pXl, *pFh, *pFl, *pGh, *pGl, *pPWh, *pPWl, *pPTh, *pPTl;
    bf16 *pXHh, *pXHl, *pOTh, *pOTl, *pRTh, *pRTl;
    float *pXH, *pSPT, *pSP, *pOUT, *pOUTT, *pRR;
    cudaGetSymbolAddress((void**)&pXh,  g_x16h);  cudaGetSymbolAddress((void**)&pXl,  g_x16l);
    cudaGetSymbolAddress((void**)&pFh,  g_F16h);  cudaGetSymbolAddress((void**)&pFl,  g_F16l);
    cudaGetSymbolAddress((void**)&pGh,  g_G16h);  cudaGetSymbolAddress((void**)&pGl,  g_G16l);
    cudaGetSymbolAddress((void**)&pPWh, g_PWh);   cudaGetSymbolAddress((void**)&pPWl, g_PWl);
    cudaGetSymbolAddress((void**)&pPTh, g_PTh);   cudaGetSymbolAddress((void**)&pPTl, g_PTl);
    cudaGetSymbolAddress((void**)&pXHh, g_XHh);   cudaGetSymbolAddress((void**)&pXHl, g_XHl);
    cudaGetSymbolAddress((void**)&pOTh, g_OTh);   cudaGetSymbolAddress((void**)&pOTl, g_OTl);
    cudaGetSymbolAddress((void**)&pRTh, g_RTh);   cudaGetSymbolAddress((void**)&pRTl, g_RTl);
    cudaGetSymbolAddress((void**)&pXH,  g_XH);
    cudaGetSymbolAddress((void**)&pSPT, g_SPT);
    cudaGetSymbolAddress((void**)&pSP,  g_SP);
    cudaGetSymbolAddress((void**)&pOUT, g_OUT);
    cudaGetSymbolAddress((void**)&pOUTT,g_OUTT);
    cudaGetSymbolAddress((void**)&pRR,  g_RR);

    cudaFuncSetAttribute(mmagemm3<true,  false>,
                         cudaFuncAttributeMaxDynamicSharedMemorySize, MM_SMEM);
    cudaFuncSetAttribute(mmagemm3<false, true>,
                         cudaFuncAttributeMaxDynamicSharedMemorySize, MM_SMEM);
    cudaFuncSetAttribute(mmagemm3<false, false>,
                         cudaFuncAttributeMaxDynamicSharedMemorySize, MM_SMEM);

    // tables + input conversion
    tab_weights<<<1, 256>>>();
    tab_ab<<<(MMAX * LMAX + 255) / 256, 256>>>();
    tab_leg<<<(MMAX * NLAT + 255) / 256, 256>>>();
    tab_F<<<(NPLANE * NLON + 255) / 256, 256>>>();
    tab_G<<<(NLON * KPAD + 255) / 256, 256>>>();
    cvt32<<<(ROWS_BCK * NLON / 4 + 255) / 256, 256>>>(x, pXh, pXl, ROWS_BCK * NLON / 4);

    // 1) forward DFT: A=x16[65536][256], B=F16[258][256], C=XH fp32 [plane][65536]
    mmagemm3<true, false><<<dim3(ROWS_BCK / 128, 3, 1), 256, MM_SMEM>>>(
        pXh, pXl, pFh, pFl, pXH, ROWS_BCK, NPLANE, NLON, NLON, NLON, ROWS_BCK, 0, 0, 0);

    // convert XH -> bf16 pair
    cvt32<<<((int)((size_t)NPLANE * ROWS_BCK / 4) + 255) / 256, 256>>>(
        pXH, pXHh, pXHl, (int)((size_t)NPLANE * ROWS_BCK / 4));

    // 2) forward Legendre (batched): A=XH16[z](256x256), B=PCTW16[m](128x256), C=SPT
    mmagemm3<false, true><<<dim3(2, 1, NPLANE), 256, MM_SMEM>>>(
        pXHh, pXHl, pPWh, pPWl, pSPT, BC, LMAX, NLAT, NLAT, NLAT, LMAX,
        ROWS_BCK, LMAX * NLAT, BC * LMAX);

    // 3) transpose to coefficient order [bc][x]
    transpose_k<<<dim3((BC * LMAX) / 32, (NPLANE + 31) / 32), dim3(32, 8)>>>(
        pSPT, pSP, NPLANE, BC * LMAX);

    // 4) channel mix
    mix_k<<<NCOEF / 32, dim3(32, 4)>>>(pSP, wgt, pOUT);

    // 5) transpose back to plane-major [plane][bo][l]
    transpose_k<<<dim3((NPLANE + 31) / 32, (BC * LMAX) / 32), dim3(32, 8)>>>(
        pOUT, pOUTT, BC * LMAX, NPLANE);

    // convert OUTT -> bf16 pair
    cvt32<<<((int)((size_t)NPLANE * BC * LMAX / 4) + 255) / 256, 256>>>(
        pOUTT, pOTh, pOTl, (int)((size_t)NPLANE * BC * LMAX / 4));

    // 6) inverse Legendre (batched): A=OUTT16[z](256x128), B=PCT_T16[m](256x128), C=RR
    mmagemm3<false, true><<<dim3(2, 2, NPLANE), 256, MM_SMEM>>>(
        pOTh, pOTl, pPTh, pPTl, pRR, BC, NLAT, LMAX, LMAX, LMAX, NLAT,
        BC * LMAX, NLAT * LMAX, ROWS_BCK);

    // transpose + convert RR[258][65536] -> RRT16[65536][264]
    transcvt<<<dim3(ROWS_BCK / 32, (KPAD + 31) / 32), dim3(32, 8)>>>(pRR, pRTh, pRTl);

    // 7) inverse DFT: A=RRT16[65536][264], B=G16[256][264], C=y fp32
    mmagemm3<false, false><<<dim3(ROWS_BCK / 128, 2, 1), 256, MM_SMEM>>>(
        pRTh, pRTl, pGh, pGl, y, ROWS_BCK, NLON, KPAD, KPAD, KPAD, NLON, 0, 0, 0);
}

// round 7
// speedup vs baseline: 1.4766x; 1.4766x over previous
#include <cuda_runtime.h>
#include <cuda_bf16.h>
#include <math.h>
#include <stdint.h>

#ifndef M_PI
#define M_PI 3.14159265358979323846
#endif

#define NLAT 256
#define NLON 256
#define LMAX 128
#define MMAX 129
#define CIN 32
#define COUT 32
#define BATCH 8
#define NPLANE 258            // 2*MMAX
#define KPAD 264              // padded plane count for S7 (mult of 8, 16B-aligned rows)
#define BC (BATCH*CIN)        // 256
#define NCOEF (2*LMAX*MMAX)   // 33024
#define ROWS_BCK (BC*NLAT)    // 65536

typedef __nv_bfloat16 bf16;

// ---------------- device scratch ----------------
__device__ float g_w[NLAT];
__device__ float g_seed[MMAX];
__device__ float g_ab[MMAX*LMAX*2];
__device__ float g_PCTW [MMAX*LMAX*NLAT];   // [m][l][k]   (B for S2)
__device__ float g_PCT_T[MMAX*NLAT*LMAX];   // [m][k][l]   (B for S6)
__device__ float g_F[NPLANE*NLON];          // Ft[plane][n]  (B for S1)
__device__ __align__(256) bf16 g_G16h[NLON*KPAD];   // Gt[n][plane] bf16 pair, ld=264
__device__ __align__(256) bf16 g_G16l[NLON*KPAD];
__device__ __align__(256) float g_XH[(size_t)NPLANE*ROWS_BCK];   // [plane][bc*256+k]
__device__ __align__(256) float g_SPT[(size_t)NPLANE*BC*LMAX];   // [plane][bc][l]
__device__ __align__(256) float g_SP [(size_t)BC*LMAX*NPLANE];   // [bc][x]
__device__ __align__(256) float g_OUT[(size_t)BC*NCOEF];         // [bo][x]
__device__ __align__(256) float g_OUTT[(size_t)NPLANE*BC*LMAX];  // [plane][bo][l]
__device__ __align__(256) float g_RR[(size_t)NPLANE*ROWS_BCK];   // [plane][bo*256+k]
__device__ __align__(256) bf16  g_RTh[(size_t)ROWS_BCK*KPAD];    // [bck][plane] ld 264
__device__ __align__(256) bf16  g_RTl[(size_t)ROWS_BCK*KPAD];

// ---------------- helpers ----------------
__device__ __forceinline__ void splitw(float v, bf16& h, bf16& l) {
    h = __float2bfloat16(v);
    l = __float2bfloat16(v - __bfloat162float(h));
}
__device__ __forceinline__ uint32_t SWZ(uint32_t off) { return off ^ ((off >> 3) & 0x70); }
__device__ __forceinline__ uint32_t smem_u32(const void* p) {
    uint32_t a;
    asm("{ .reg .u64 t; cvta.to.shared.u64 t, %1; cvt.u32.u64 %0, t; }" : "=r"(a) : "l"(p));
    return a;
}
__device__ __forceinline__ void ldsm4(uint32_t* r, uint32_t addr) {
    asm volatile("ldmatrix.sync.aligned.m8n8.x4.shared.b16 {%0,%1,%2,%3}, [%4];"
        : "=r"(r[0]), "=r"(r[1]), "=r"(r[2]), "=r"(r[3]) : "r"(addr));
}
__device__ __forceinline__ void mma_bf16(float* c, const uint32_t* a, uint32_t b0, uint32_t b1) {
    asm volatile("mma.sync.aligned.m16n8k16.row.col.f32.bf16.bf16.f32 "
        "{%0,%1,%2,%3}, {%4,%5,%6,%7}, {%8,%9}, {%0,%1,%2,%3};"
        : "+f"(c[0]), "+f"(c[1]), "+f"(c[2]), "+f"(c[3])
        : "r"(a[0]), "r"(a[1]), "r"(a[2]), "r"(a[3]), "r"(b0), "r"(b1));
}
__device__ __forceinline__ void split2(float a, float b, uint32_t& hi, uint32_t& lo) {
    __nv_bfloat162 h = __floats2bfloat162_rn(a, b);
    hi = *reinterpret_cast<uint32_t*>(&h);
    __nv_bfloat162 l = __floats2bfloat162_rn(a - __bfloat162float(h.x),
                                             b - __bfloat162float(h.y));
    lo = *reinterpret_cast<uint32_t*>(&l);
}

// ---------------- table builders ----------------
__global__ void tab_weights() {
    int j = threadIdx.x;
    double tj = M_PI * (double)j / (double)(NLAT - 1);
    double S = 0.0;
    for (int k = 1; k <= (NLAT - 1) / 2; k++)
        S += cos(2.0 * tj * (double)k) * (2.0 / (4.0 * (double)k * k - 1.0));
    double c = (j == 0 || j == NLAT - 1) ? 1.0 : 2.0;
    g_w[j] = (float)(c / (double)(NLAT - 1) * (1.0 - S));
}

__global__ void tab_ab() {
    int t = blockIdx.x * blockDim.x + threadIdx.x;
    if (t >= MMAX * LMAX) return;
    int m = t / LMAX, l = t % LMAX;
    if (l == 0)
        g_seed[m] = (m >= 1) ? (float)sqrt((2.0 * m + 1.0) / (2.0 * m)) : 0.f;
    float a = 0.f, b = 0.f;
    if (l >= m + 2) {
        double ld = l, md = m;
        a = (float)sqrt((4.0 * ld * ld - 1.0) / (ld * ld - md * md));
        b = (float)sqrt(((ld - 1.0) * (ld - 1.0) - md * md) /
                        (4.0 * (ld - 1.0) * (ld - 1.0) - 1.0));
    }
    g_ab[t * 2] = a;
    g_ab[t * 2 + 1] = b;
}

// writes PCTW[m][l][k] and PCT_T[m][k][l] (fp32)
__global__ void tab_leg() {
    int t = blockIdx.x * blockDim.x + threadIdx.x;
    if (t >= MMAX * NLAT) return;
    int m = t / NLAT, k = t % NLAT;
    double td = M_PI * (double)k / (double)(NLAT - 1);
    float ct = (float)cos(td), st = (float)sin(td);
    float w = g_w[k];
    float pmm = 0.28209479177387814f;  // 1/sqrt(4*pi)
    for (int mm = 1; mm <= m; mm++) pmm *= -g_seed[mm] * st;

    float* pw = g_PCTW + (size_t)(m * LMAX) * NLAT + k;     // stride NLAT per l
    float* pt = g_PCT_T + ((size_t)m * NLAT + k) * LMAX;    // stride 1 per l
    for (int l = 0; l < m && l < LMAX; l++) { pw[0] = 0.f; pt[l] = 0.f; pw += NLAT; }
    if (m < LMAX) {
        float pm2 = pmm;
        pw[0] = pm2 * w; pt[m] = pm2; pw += NLAT;
        if (m + 1 < LMAX) {
            float pm1 = sqrtf(2.f * m + 3.f) * ct * pm2;
            pw[0] = pm1 * w; pt[m + 1] = pm1; pw += NLAT;
            for (int l = m + 2; l < LMAX; l++) {
                float a = g_ab[(m * LMAX + l) * 2];
                float b = g_ab[(m * LMAX + l) * 2 + 1];
                float pn = a * (ct * pm1 - b * pm2);
                pw[0] = pn * w; pt[l] = pn; pw += NLAT;
                pm2 = pm1; pm1 = pn;
            }
        }
    }
}

// Forward DFT matrix, plane-major fp32: Ft[2m+r][n]
__global__ void tab_F() {
    int t = blockIdx.x * blockDim.x + threadIdx.x;
    if (t >= NPLANE * NLON) return;
    int p = t / NLON, n = t % NLON;
    int m = p >> 1, r = p & 1;
    double ang = 2.0 * M_PI * (double)((m * n) & (NLON - 1)) / (double)NLON;
    double s = 2.0 * M_PI / (double)NLON;
    g_F[t] = (float)(r == 0 ? s * cos(ang) : -s * sin(ang));
}

// Inverse DFT matrix, lon-major bf16 pair: Gt[n][2m+r], ld=KPAD, zero-padded
__global__ void tab_G() {
    int t = blockIdx.x * blockDim.x + threadIdx.x;
    if (t >= NLON * KPAD) return;
    int n = t / KPAD, p = t % KPAD;
    float v = 0.f;
    if (p < NPLANE) {
        int m = p >> 1, r = p & 1;
        double c = (m == 0 || m == MMAX - 1) ? 1.0 : 2.0;
        double ang = 2.0 * M_PI * (double)((m * n) & (NLON - 1)) / (double)NLON;
        v = (float)(r == 0 ? c * cos(ang) : -c * sin(ang));
    }
    bf16 h, l; splitw(v, h, l);
    g_G16h[t] = h; g_G16l[t] = l;
}

// ---------------- transpose + convert: RR[258][65536] -> RRT[65536][264] bf16 pair ----
__global__ void transcvt(const float* __restrict__ in, bf16* __restrict__ hi,
                         bf16* __restrict__ lo) {
    __shared__ float t[32][33];
    int c0 = blockIdx.x * 32;   // over ROWS_BCK
    int r0 = blockIdx.y * 32;   // over KPAD
    int tx = threadIdx.x;
    for (int j = threadIdx.y; j < 32; j += 8) {
        int r = r0 + j;
        t[j][tx] = (r < NPLANE) ? in[(size_t)r * ROWS_BCK + c0 + tx] : 0.f;
    }
    __syncthreads();
    for (int j = threadIdx.y; j < 32; j += 8) {
        int outc = r0 + tx;
        if (outc < KPAD) {
            float v = t[tx][j];
            bf16 h, l; splitw(v, h, l);
            size_t o = (size_t)(c0 + j) * KPAD + outc;
            hi[o] = h; lo[o] = l;
        }
    }
}

// ================= GEMM A (R5-proven): fp32 operands, convert in-loop ==========
// C[M,N] = A*B; tile 128x128, BK=64; 256 thr, 8 warps (2m x 4n), warp 64x32.
// A[m][k]; B[n][k] (K-major rows).  D = Ahi*Bhi + Ahi*Blo + Alo*Bhi (fp32 acc).
#define MM_SMEM 65536
#define OFF_ALO 16384u
#define OFF_BHI 32768u
#define OFF_BLO 49152u

template<bool CTRANS, bool BHALF>
__global__ void __launch_bounds__(256, 2) mmagemm(
    const float* __restrict__ A, const float* __restrict__ B, float* __restrict__ C,
    int M, int N, int K, int lda, int ldb, int ldc, int sA, int sB, int sC)
{
    extern __shared__ char smem[];
    const uint32_t sbase = smem_u32(smem);
    const int tid = threadIdx.x;
    const int wid = tid >> 5;
    const int lane = tid & 31;

    int z = blockIdx.z;
    A += (size_t)z * sA;
    B += (size_t)(BHALF ? (z >> 1) : z) * sB;
    C += (size_t)z * sC;
    const int bm = blockIdx.x * 128;
    const int bn = blockIdx.y * 128;

    const int wm = wid & 1;
    const int wn = wid >> 1;

    float acc[4][4][4] = {};

    const uint32_t aBase = (uint32_t)((wm * 64 + (lane & 15)) * 128 + ((lane >> 4) << 4));
    const uint32_t bBase = (uint32_t)((wn * 32 + (lane & 15)) * 128 + ((lane >> 4) << 4));

    const int NK = (K + 63) >> 6;
    for (int kt = 0; kt < NK; kt++) {
        const int k0 = kt << 6;

        // ---- load + convert A tile ----
        {
            int r = tid >> 1;
            int kh = (tid & 1) << 5;
            const float* p = A + (size_t)(bm + r) * lda + k0 + kh;
            #pragma unroll
            for (int q = 0; q < 8; q++) {
                int gk = k0 + kh + q * 4;
                float4 v;
                if (gk + 3 < K) v = *reinterpret_cast<const float4*>(p + q * 4);
                else {
                    v.x = (gk + 0 < K) ? p[q * 4 + 0] : 0.f;
                    v.y = (gk + 1 < K) ? p[q * 4 + 1] : 0.f;
                    v.z = (gk + 2 < K) ? p[q * 4 + 2] : 0.f;
                    v.w = (gk + 3 < K) ? p[q * 4 + 3] : 0.f;
                }
                uint32_t h0, l0, h1, l1;
                split2(v.x, v.y, h0, l0);
                split2(v.z, v.w, h1, l1);
                uint32_t off = SWZ((uint32_t)(r * 128 + (kh + q * 4) * 2));
                *reinterpret_cast<uint2*>(smem + off)           = make_uint2(h0, h1);
                *reinterpret_cast<uint2*>(smem + OFF_ALO + off) = make_uint2(l0, l1);
            }
        }
        // ---- load + convert B tile ----
        {
            int r = tid >> 1;
            int kh = (tid & 1) << 5;
            int gn = bn + r;
            const float* p = B + (size_t)gn * ldb + k0 + kh;
            bool nok = gn < N;
            #pragma unroll
            for (int q = 0; q < 8; q++) {
                int gk = k0 + kh + q * 4;
                float4 v = make_float4(0.f, 0.f, 0.f, 0.f);
                if (nok) {
                    if (gk + 3 < K) v = *reinterpret_cast<const float4*>(p + q * 4);
                    else {
                        if (gk + 0 < K) v.x = p[q * 4 + 0];
                        if (gk + 1 < K) v.y = p[q * 4 + 1];
                        if (gk + 2 < K) v.z = p[q * 4 + 2];
                        if (gk + 3 < K) v.w = p[q * 4 + 3];
                    }
                }
                uint32_t h0, l0, h1, l1;
                split2(v.x, v.y, h0, l0);
                split2(v.z, v.w, h1, l1);
                uint32_t off = SWZ((uint32_t)(r * 128 + (kh + q * 4) * 2));
                *reinterpret_cast<uint2*>(smem + OFF_BHI + off) = make_uint2(h0, h1);
                *reinterpret_cast<uint2*>(smem + OFF_BLO + off) = make_uint2(l0, l1);
            }
        }
        __syncthreads();

        // ---- MMA over 4 k-steps of 16 ----
        #pragma unroll
        for (int ks = 0; ks < 4; ks++) {
            uint32_t kb = (uint32_t)(ks * 32);

            uint32_t ah[4][4];
            #pragma unroll
            for (int mi = 0; mi < 4; mi++)
                ldsm4(ah[mi], sbase + SWZ(aBase + mi * 2048 + kb));

            uint32_t bh[4][2];
            #pragma unroll
            for (int g = 0; g < 2; g++) {
                uint32_t t[4];
                ldsm4(t, sbase + OFF_BHI + SWZ(bBase + g * 2048 + kb));
                bh[2 * g][0] = t[0]; bh[2 * g][1] = t[2];
                bh[2 * g + 1][0] = t[1]; bh[2 * g + 1][1] = t[3];
            }
            #pragma unroll
            for (int mi = 0; mi < 4; mi++)
                #pragma unroll
                for (int nb = 0; nb < 4; nb++)
                    mma_bf16(acc[mi][nb], ah[mi], bh[nb][0], bh[nb][1]);

            #pragma unroll
            for (int g = 0; g < 2; g++) {
                uint32_t t[4];
                ldsm4(t, sbase + OFF_BLO + SWZ(bBase + g * 2048 + kb));
                #pragma unroll
                for (int mi = 0; mi < 4; mi++) {
                    mma_bf16(acc[mi][2 * g],     ah[mi], t[0], t[2]);
                    mma_bf16(acc[mi][2 * g + 1], ah[mi], t[1], t[3]);
                }
            }
            #pragma unroll
            for (int mi = 0; mi < 4; mi++) {
                uint32_t al[4];
                ldsm4(al, sbase + SWZ(aBase + mi * 2048 + kb) + OFF_ALO);
                #pragma unroll
                for (int nb = 0; nb < 4; nb++)
                    mma_bf16(acc[mi][nb], al, bh[nb][0], bh[nb][1]);
            }
        }
        __syncthreads();
    }

    // ---- epilogue ----
    #pragma unroll
    for (int mi = 0; mi < 4; mi++) {
        #pragma unroll
        for (int nb = 0; nb < 4; nb++) {
            int m0 = bm + wm * 64 + mi * 16 + (lane >> 2);
            int n0 = bn + wn * 32 + nb * 8 + ((lane & 3) << 1);
            float* a = acc[mi][nb];
            if (!CTRANS) {
                *reinterpret_cast<float2*>(&C[(size_t)m0 * ldc + n0]) =
                    make_float2(a[0], a[1]);
                *reinterpret_cast<float2*>(&C[(size_t)(m0 + 8) * ldc + n0]) =
                    make_float2(a[2], a[3]);
            } else {
                if (n0 < N) {
                    C[(size_t)n0 * ldc + m0]     = a[0];
                    C[(size_t)n0 * ldc + m0 + 8] = a[2];
                }
                if (n0 + 1 < N) {
                    C[(size_t)(n0 + 1) * ldc + m0]     = a[1];
                    C[(size_t)(n0 + 1) * ldc + m0 + 8] = a[3];
                }
            }
        }
    }
}

// ================= GEMM B (presplit operands) — used by S7 only ================
__global__ void __launch_bounds__(256, 2) mmagemm3(
    const bf16* __restrict__ Ahi, const bf16* __restrict__ Alo,
    const bf16* __restrict__ Bhi, const bf16* __restrict__ Blo,
    float* __restrict__ C,
    int M, int N, int K, int lda, int ldb, int ldc)
{
    extern __shared__ char smem[];
    const uint32_t sbase = smem_u32(smem);
    const int tid = threadIdx.x;
    const int wid = tid >> 5;
    const int lane = tid & 31;

    const int bm = blockIdx.x * 128;
    const int bn = blockIdx.y * 128;
    const int wm = wid & 1;
    const int wn = wid >> 1;

    float acc[4][4][4] = {};

    const uint32_t aBase = (uint32_t)((wm * 64 + (lane & 15)) * 128 + ((lane >> 4) << 4));
    const uint32_t bBase = (uint32_t)((wn * 32 + (lane & 15)) * 128 + ((lane >> 4) << 4));

    const int r  = tid >> 1;
    const int kh = (tid & 1) << 5;

    const int NK = (K + 63) >> 6;
    for (int kt = 0; kt < NK; kt++) {
        const int k0 = kt << 6;
        {
            size_t ro = (size_t)(bm + r) * lda + k0 + kh;
            const uint4* ph = reinterpret_cast<const uint4*>(Ahi + ro);
            const uint4* pl = reinterpret_cast<const uint4*>(Alo + ro);
            #pragma unroll
            for (int j = 0; j < 4; j++) {
                int gk = k0 + kh + j * 8;
                uint4 vh = make_uint4(0, 0, 0, 0), vl = make_uint4(0, 0, 0, 0);
                if (gk < K) { vh = ph[j]; vl = pl[j]; }
                uint32_t off = SWZ((uint32_t)(r * 128 + kh * 2 + j * 16));
                *reinterpret_cast<uint4*>(smem + off)           = vh;
                *reinterpret_cast<uint4*>(smem + OFF_ALO + off) = vl;
            }
        }
        {
            int gn = bn + r;
            bool nok = gn < N;
            size_t ro = (size_t)gn * ldb + k0 + kh;
            const uint4* ph = reinterpret_cast<const uint4*>(Bhi + ro);
            const uint4* pl = reinterpret_cast<const uint4*>(Blo + ro);
            #pragma unroll
            for (int j = 0; j < 4; j++) {
                int gk = k0 + kh + j * 8;
                uint4 vh = make_uint4(0, 0, 0, 0), vl = make_uint4(0, 0, 0, 0);
                if (nok && gk < K) { vh = ph[j]; vl = pl[j]; }
                uint32_t off = SWZ((uint32_t)(r * 128 + kh * 2 + j * 16));
                *reinterpret_cast<uint4*>(smem + OFF_BHI + off) = vh;
                *reinterpret_cast<uint4*>(smem + OFF_BLO + off) = vl;
            }
        }
        __syncthreads();

        #pragma unroll
        for (int ks = 0; ks < 4; ks++) {
            uint32_t kb = (uint32_t)(ks * 32);
            uint32_t ah[4][4];
            #pragma unroll
            for (int mi = 0; mi < 4; mi++)
                ldsm4(ah[mi], sbase + SWZ(aBase + mi * 2048 + kb));
            uint32_t bh[4][2];
            #pragma unroll
            for (int g = 0; g < 2; g++) {
                uint32_t t[4];
                ldsm4(t, sbase + OFF_BHI + SWZ(bBase + g * 2048 + kb));
                bh[2 * g][0] = t[0]; bh[2 * g][1] = t[2];
                bh[2 * g + 1][0] = t[1]; bh[2 * g + 1][1] = t[3];
            }
            #pragma unroll
            for (int mi = 0; mi < 4; mi++)
                #pragma unroll
                for (int nb = 0; nb < 4; nb++)
                    mma_bf16(acc[mi][nb], ah[mi], bh[nb][0], bh[nb][1]);
            #pragma unroll
            for (int g = 0; g < 2; g++) {
                uint32_t t[4];
                ldsm4(t, sbase + OFF_BLO + SWZ(bBase + g * 2048 + kb));
                #pragma unroll
                for (int mi = 0; mi < 4; mi++) {
                    mma_bf16(acc[mi][2 * g],     ah[mi], t[0], t[2]);
                    mma_bf16(acc[mi][2 * g + 1], ah[mi], t[1], t[3]);
                }
            }
            #pragma unroll
            for (int mi = 0; mi < 4; mi++) {
                uint32_t al[4];
                ldsm4(al, sbase + SWZ(aBase + mi * 2048 + kb) + OFF_ALO);
                #pragma unroll
                for (int nb = 0; nb < 4; nb++)
                    mma_bf16(acc[mi][nb], al, bh[nb][0], bh[nb][1]);
            }
        }
        __syncthreads();
    }

    #pragma unroll
    for (int mi = 0; mi < 4; mi++) {
        #pragma unroll
        for (int nb = 0; nb < 4; nb++) {
            int m0 = bm + wm * 64 + mi * 16 + (lane >> 2);
            int n0 = bn + wn * 32 + nb * 8 + ((lane & 3) << 1);
            float* a = acc[mi][nb];
            *reinterpret_cast<float2*>(&C[(size_t)m0 * ldc + n0]) =
                make_float2(a[0], a[1]);
            *reinterpret_cast<float2*>(&C[(size_t)(m0 + 8) * ldc + n0]) =
                make_float2(a[2], a[3]);
        }
    }
}

// ---------------- tiled transpose: in[R][Cc] -> out[Cc][R] ----------------
__global__ void transpose_k(const float* __restrict__ in, float* __restrict__ out,
                            int R, int Cc) {
    __shared__ float t[32][33];
    int c0 = blockIdx.x * 32, r0 = blockIdx.y * 32;
    int tx = threadIdx.x;
    for (int j = threadIdx.y; j < 32; j += 8) {
        int r = r0 + j, c = c0 + tx;
        if (r < R && c < Cc) t[j][tx] = in[(size_t)r * Cc + c];
    }
    __syncthreads();
    for (int j = threadIdx.y; j < 32; j += 8) {
        int c = c0 + j, r = r0 + tx;
        if (c < Cc && r < R) out[(size_t)c * R + r] = t[tx][j];
    }
}

// ---------------- channel mix ----------------
__global__ void __launch_bounds__(128) mix_k(const float* __restrict__ spec,
                                             const float* __restrict__ wgt,
                                             float* __restrict__ out) {
    __shared__ float s_sp[8][32][32];
    __shared__ float s_w[32][4][32];
    int x0 = blockIdx.x * 32;
    int tx = threadIdx.x, ty = threadIdx.y;
    int tid = ty * 32 + tx;
    int warp = tid >> 5, wl = tid & 31;
    for (int row = warp; row < 256; row += 4)
        s_sp[row >> 5][row & 31][wl] = spec[row * NCOEF + x0 + wl];
    for (int oc = 0; oc < 8; oc++) {
        __syncthreads();
        for (int r = warp; r < 128; r += 4) {
            int i = r >> 2, ol = r & 3;
            s_w[i][ol][wl] = wgt[(i * COUT + oc * 4 + ol) * NCOEF + x0 + wl];
        }
        __syncthreads();
        float acc[8] = {};
        #pragma unroll
        for (int i = 0; i < 32; i++) {
            float wv = s_w[i][ty][tx];
            #pragma unroll
            for (int b = 0; b < 8; b++) acc[b] += s_sp[b][i][tx] * wv;
        }
        int o = oc * 4 + ty;
        #pragma unroll
        for (int b = 0; b < 8; b++)
            out[(b * COUT + o) * NCOEF + x0 + tx] = acc[b];
    }
}

// ---------------- launch ----------------
extern "C" void kernel_launch(void* const* d_in, const int* in_sizes, int n_in,
                              void* d_out, int out_size) {
    const float* x   = (const float*)d_in[0];   // [8,32,256,256]
    const float* wgt = (const float*)d_in[1];   // [32,32,33024]
    float* y = (float*)d_out;                   // [8,32,256,256]

    float *pPCTW, *pPCT_T, *pF, *pXH, *pSPT, *pSP, *pOUT, *pOUTT, *pRR;
    bf16 *pGh, *pGl, *pRTh, *pRTl;
    cudaGetSymbolAddress((void**)&pPCTW,  g_PCTW);
    cudaGetSymbolAddress((void**)&pPCT_T, g_PCT_T);
    cudaGetSymbolAddress((void**)&pF,     g_F);
    cudaGetSymbolAddress((void**)&pGh,    g_G16h);
    cudaGetSymbolAddress((void**)&pGl,    g_G16l);
    cudaGetSymbolAddress((void**)&pXH,    g_XH);
    cudaGetSymbolAddress((void**)&pSPT,   g_SPT);
    cudaGetSymbolAddress((void**)&pSP,    g_SP);
    cudaGetSymbolAddress((void**)&pOUT,   g_OUT);
    cudaGetSymbolAddress((void**)&pOUTT,  g_OUTT);
    cudaGetSymbolAddress((void**)&pRR,    g_RR);
    cudaGetSymbolAddress((void**)&pRTh,   g_RTh);
    cudaGetSymbolAddress((void**)&pRTl,   g_RTl);

    cudaFuncSetAttribute(mmagemm<true,  false>,
                         cudaFuncAttributeMaxDynamicSharedMemorySize, MM_SMEM);
    cudaFuncSetAttribute(mmagemm<false, true>,
                         cudaFuncAttributeMaxDynamicSharedMemorySize, MM_SMEM);
    cudaFuncSetAttribute(mmagemm3,
                         cudaFuncAttributeMaxDynamicSharedMemorySize, MM_SMEM);

    // tables
    tab_weights<<<1, 256>>>();
    tab_ab<<<(MMAX * LMAX + 255) / 256, 256>>>();
    tab_leg<<<(MMAX * NLAT + 255) / 256, 256>>>();
    tab_F<<<(NPLANE * NLON + 255) / 256, 256>>>();
    tab_G<<<(NLON * KPAD + 255) / 256, 256>>>();

    // 1) forward DFT: A=x[65536][256] fp32, B=Ft[258][256] fp32, C=XH[plane][65536]
    mmagemm<true, false><<<dim3(ROWS_BCK / 128, 3, 1), 256, MM_SMEM>>>(
        x, pF, pXH, ROWS_BCK, NPLANE, NLON, NLON, NLON, ROWS_BCK, 0, 0, 0);

    // 2) forward Legendre (batched): A=XH[z](256x256), B=PCTW[m](128x256), C=SPT
    mmagemm<false, true><<<dim3(2, 1, NPLANE), 256, MM_SMEM>>>(
        pXH, pPCTW, pSPT, BC, LMAX, NLAT, NLAT, NLAT, LMAX,
        ROWS_BCK, LMAX * NLAT, BC * LMAX);

    // 3) transpose to coefficient order [bc][x]
    transpose_k<<<dim3((BC * LMAX) / 32, (NPLANE + 31) / 32), dim3(32, 8)>>>(
        pSPT, pSP, NPLANE, BC * LMAX);

    // 4) channel mix
    mix_k<<<NCOEF / 32, dim3(32, 4)>>>(pSP, wgt, pOUT);

    // 5) transpose back to plane-major [plane][bo][l]
    transpose_k<<<dim3((NPLANE + 31) / 32, (BC * LMAX) / 32), dim3(32, 8)>>>(
        pOUT, pOUTT, BC * LMAX, NPLANE);

    // 6) inverse Legendre (batched): A=OUTT[z](256x128), B=PCT_T[m](256x128), C=RR
    mmagemm<false, true><<<dim3(2, 2, NPLANE), 256, MM_SMEM>>>(
        pOUTT, pPCT_T, pRR, BC, NLAT, LMAX, LMAX, LMAX, NLAT,
        BC * LMAX, NLAT * LMAX, ROWS_BCK);

    // transpose + convert RR[258][65536] -> RRT16[65536][264] bf16 pairs
    transcvt<<<dim3(ROWS_BCK / 32, (KPAD + 31) / 32), dim3(32, 8)>>>(pRR, pRTh, pRTl);

    // 7) inverse DFT (presplit NT): A=RRT16, B=G16[256][264], C=y
    mmagemm3<<<dim3(ROWS_BCK / 128, 2, 1), 256, MM_SMEM>>>(
        pRTh, pRTl, pGh, pGl, y, ROWS_BCK, NLON, KPAD, KPAD, KPAD, NLON);
}